// round 4
// baseline (speedup 1.0000x reference)
#include <cuda_runtime.h>
#include <math.h>

// Problem constants
#define BB   2
#define SS   256
#define INP  80
#define HID  128
#define F2   256
#define G4   512   // 4*HID
#define NCC  40
#define WSEG 64

// ---------------- device scratch (no allocation allowed) ----------------
__device__ float g_WihT0[2][INP][G4];    // [dir][i][g]
__device__ float g_WihT1[2][F2][G4];
__device__ float g_WhhT[2][2][HID][G4];  // [layer][dir][k][g]
__device__ float g_pre[2][BB][SS][G4];   // [dir][b][s][g]  (reused per layer)
__device__ float g_rnn[2][BB][SS][F2];   // [layer][b][s][f]
__device__ float g_cum[BB][SS][F2];
__device__ float g_WcT[F2][128];         // w_s1 c-part transposed, o padded 100->128 (zeros)
__device__ float g_WdT[F2][128];
__device__ float g_WeT[F2][128];
__device__ float g_wc1T[F2][80];
__device__ float g_wb1T[F2][80];
__device__ float g_dterm[BB][SS][128];   // prelu(rnn_i)@Wd^T + b_s1 (padded)
__device__ float g_eterm[BB][SS][128];   // prelu(rnn_j)@We^T
__device__ float g_scores[BB][SS][SS];   // scores[b][i][j], c = cum_j - cum_i
__device__ int   g_backptr[BB][SS];

__device__ __forceinline__ float sigf(float x) { return 1.0f / (1.0f + expf(-x)); }
__device__ __forceinline__ float preluf(float x, float a) { return x >= 0.0f ? x : a * x; }

// ---------------- prep: transpose weights into friendly layouts ----------------
__global__ void prep_k(const float* __restrict__ wih0f, const float* __restrict__ whh0f,
                       const float* __restrict__ wih0b, const float* __restrict__ whh0b,
                       const float* __restrict__ wih1f, const float* __restrict__ whh1f,
                       const float* __restrict__ wih1b, const float* __restrict__ whh1b,
                       const float* __restrict__ ws1,  const float* __restrict__ wc1,
                       const float* __restrict__ wb1)
{
    int idx = blockIdx.x * blockDim.x + threadIdx.x;
    int n = gridDim.x * blockDim.x;
    for (int p = idx; p < 2 * INP * G4; p += n) {
        int d = p / (INP * G4), r = p % (INP * G4), i = r / G4, g = r % G4;
        g_WihT0[d][i][g] = (d ? wih0b : wih0f)[g * INP + i];
    }
    for (int p = idx; p < 2 * F2 * G4; p += n) {
        int d = p / (F2 * G4), r = p % (F2 * G4), i = r / G4, g = r % G4;
        g_WihT1[d][i][g] = (d ? wih1b : wih1f)[g * F2 + i];
    }
    for (int p = idx; p < 2 * 2 * HID * G4; p += n) {
        int l = p / (2 * HID * G4), r = p % (2 * HID * G4);
        int d = r / (HID * G4), r2 = r % (HID * G4), k = r2 / G4, g = r2 % G4;
        const float* w = l ? (d ? whh1b : whh1f) : (d ? whh0b : whh0f);
        g_WhhT[l][d][k][g] = w[g * HID + k];
    }
    for (int p = idx; p < F2 * 128; p += n) {
        int k = p / 128, o = p % 128;
        g_WcT[k][o] = (o < 100) ? ws1[o * 768 + k]        : 0.0f;
        g_WdT[k][o] = (o < 100) ? ws1[o * 768 + 256 + k]  : 0.0f;
        g_WeT[k][o] = (o < 100) ? ws1[o * 768 + 512 + k]  : 0.0f;
    }
    for (int p = idx; p < F2 * 80; p += n) {
        int k = p / 80, o = p % 80;
        g_wc1T[k][o] = wc1[o * F2 + k];
        g_wb1T[k][o] = wb1[o * F2 + k];
    }
}

// ---------------- input projection: pre = x @ Wih^T + b ----------------
template <int INDIM>
__global__ void inproj_k(const float* __restrict__ x0,
                         const float* __restrict__ bias_f, const float* __restrict__ bias_b,
                         int layer)
{
    int st = blockIdx.x * 8, b = blockIdx.y, d = blockIdx.z, g = threadIdx.x; // 512 threads
    __shared__ float xs[8][INDIM];
    const float* xin = layer ? &g_rnn[0][0][0][0] : x0;
    for (int p = g; p < 8 * INDIM; p += 512) {
        int ss = p / INDIM, i = p % INDIM;
        xs[ss][i] = xin[(b * SS + st + ss) * INDIM + i];
    }
    __syncthreads();
    const float* W = (INDIM == INP) ? &g_WihT0[d][0][0] : &g_WihT1[d][0][0];
    float bg = (d ? bias_b : bias_f)[g];
    float acc[8];
#pragma unroll
    for (int ss = 0; ss < 8; ss++) acc[ss] = bg;
    for (int i = 0; i < INDIM; i++) {
        float w = W[i * G4 + g];
#pragma unroll
        for (int ss = 0; ss < 8; ss++) acc[ss] = fmaf(xs[ss][i], w, acc[ss]);
    }
#pragma unroll
    for (int ss = 0; ss < 8; ss++) g_pre[d][b][st + ss][g] = acc[ss];
}

// ---------------- LSTM recurrence: one CTA per (b, dir), 256 threads ----------------
__global__ void __launch_bounds__(256) recur_k(int layer)
{
    int b = blockIdx.x, d = blockIdx.y, t = threadIdx.x; // 256 threads, 2 gate outputs each
    __shared__ float hs[HID];
    __shared__ float gs[G4];
    float c = 0.0f;
    if (t < HID) hs[t] = 0.0f;
    __syncthreads();
    const float2* __restrict__ W2 = reinterpret_cast<const float2*>(&g_WhhT[layer][d][0][0]); // [k][256] float2
    const float2* __restrict__ preB = reinterpret_cast<const float2*>(&g_pre[d][b][0][0]);
    float* out = &g_rnn[layer][b][0][0];
    const float4* hs4 = reinterpret_cast<const float4*>(hs);
    for (int step = 0; step < SS; ++step) {
        int s = d ? (SS - 1 - step) : step;
        float2 p = preB[s * 256 + t];
        float a0 = p.x, a1 = p.y;
#pragma unroll 8
        for (int k4 = 0; k4 < 32; k4++) {
            float4 h = hs4[k4];
            float2 w0 = W2[(k4 * 4 + 0) * 256 + t];
            float2 w1 = W2[(k4 * 4 + 1) * 256 + t];
            float2 w2 = W2[(k4 * 4 + 2) * 256 + t];
            float2 w3 = W2[(k4 * 4 + 3) * 256 + t];
            a0 = fmaf(h.x, w0.x, a0); a1 = fmaf(h.x, w0.y, a1);
            a0 = fmaf(h.y, w1.x, a0); a1 = fmaf(h.y, w1.y, a1);
            a0 = fmaf(h.z, w2.x, a0); a1 = fmaf(h.z, w2.y, a1);
            a0 = fmaf(h.w, w3.x, a0); a1 = fmaf(h.w, w3.y, a1);
        }
        gs[2 * t] = a0; gs[2 * t + 1] = a1;
        __syncthreads();
        if (t < HID) {
            float gi = gs[t], gf = gs[HID + t], gg = gs[2 * HID + t], go = gs[3 * HID + t];
            c = sigf(gf) * c + sigf(gi) * tanhf(gg);
            float h = sigf(go) * tanhf(c);
            hs[t] = h;
            out[s * F2 + d * HID + t] = h;
        }
        __syncthreads();
    }
}

// ---------------- cumsum over time ----------------
__global__ void cumsum_k()
{
    int b = blockIdx.x, k = threadIdx.x; // 256
    float run = 0.0f;
#pragma unroll 4
    for (int s = 0; s < SS; s++) {
        run += g_rnn[1][b][s][k];
        g_cum[b][s][k] = run;
    }
}

// ---------------- dterm/eterm precompute ----------------
__global__ void determ_k(const float* __restrict__ a_s0p, const float* __restrict__ bs1)
{
    int s = blockIdx.x, b = blockIdx.y, t = threadIdx.x; // 128
    __shared__ float pr[F2];
    float a0 = *a_s0p;
    for (int p = t; p < F2; p += 128) pr[p] = preluf(g_rnn[1][b][s][p], a0);
    __syncthreads();
    float ad = 0.0f, ae = 0.0f;
    for (int k = 0; k < F2; k++) {
        float p = pr[k];
        ad = fmaf(p, g_WdT[k][t], ad);
        ae = fmaf(p, g_WeT[k][t], ae);
    }
    g_dterm[b][s][t] = ad + ((t < 100) ? bs1[t] : 0.0f);
    g_eterm[b][s][t] = ae;
}

// ---------------- cls / bin MLPs ----------------
__global__ void clsbin_k(const float* __restrict__ ac0, const float* __restrict__ bc1,
                         const float* __restrict__ ac1, const float* __restrict__ wc2,
                         const float* __restrict__ bc2,
                         const float* __restrict__ ab0, const float* __restrict__ bb1,
                         const float* __restrict__ ab1, const float* __restrict__ wb2,
                         const float* __restrict__ bb2, float* __restrict__ out)
{
    int s = blockIdx.x, b = blockIdx.y, t = threadIdx.x; // 128
    __shared__ float pr[F2];
    __shared__ float h1[80];
    // CLS
    float a = *ac0;
    for (int p = t; p < F2; p += 128) pr[p] = preluf(g_rnn[1][b][s][p], a);
    __syncthreads();
    if (t < 80) {
        float acc = bc1[t];
        for (int k = 0; k < F2; k++) acc = fmaf(pr[k], g_wc1T[k][t], acc);
        h1[t] = preluf(acc, *ac1);
    }
    __syncthreads();
    if (t < NCC) {
        float acc = bc2[t];
        for (int q = 0; q < 80; q++) acc = fmaf(h1[q], wc2[t * 80 + q], acc);
        out[(b * SS + s) * NCC + t] = acc;
    }
    __syncthreads();
    // BIN
    a = *ab0;
    for (int p = t; p < F2; p += 128) pr[p] = preluf(g_rnn[1][b][s][p], a);
    __syncthreads();
    if (t < 80) {
        float acc = bb1[t];
        for (int k = 0; k < F2; k++) acc = fmaf(pr[k], g_wb1T[k][t], acc);
        h1[t] = preluf(acc, *ab1);
    }
    __syncthreads();
    if (t < 2) {
        float acc = bb2[t];
        for (int q = 0; q < 80; q++) acc = fmaf(h1[q], wb2[t * 80 + q], acc);
        out[20480 + (b * SS + s) * 2 + t] = acc;
    }
}

// ---------------- pairwise scores: block = (i, b), 256 threads ----------------
// Register-blocked: each thread computes 4 j's x 8 outputs (32 accumulators).
// k split into two 128-halves so the 64-row T tile fits in static smem.
#define TROW 132   // 128 k-half + 4 pad (bank-shift 4/row)
__global__ void __launch_bounds__(256) scores_k(const float* __restrict__ a_s0p,
                         const float* __restrict__ a_s1p,
                         const float* __restrict__ ws2, const float* __restrict__ bs2)
{
    int i = blockIdx.x, b = blockIdx.y, tid = threadIdx.x;
    int oq = tid & 15, jg = tid >> 4;   // 16 output-groups x 16 j-groups(4 j)
    __shared__ float cum_i[F2];
    __shared__ float T[64 * TROW];
    float a0 = *a_s0p, a1 = *a_s1p;
    for (int p = tid; p < F2; p += 256) cum_i[p] = g_cum[b][i][p];
    float dt[8], w2v[8];
#pragma unroll
    for (int r = 0; r < 8; r++) {
        int o = oq * 8 + r;
        dt[r] = g_dterm[b][i][o];
        w2v[r] = (o < 100) ? ws2[o] : 0.0f;
    }
    float bs2v = bs2[0];
    __syncthreads();
    const float4* __restrict__ W4 = reinterpret_cast<const float4*>(&g_WcT[0][0]);
    for (int tile = 0; tile < 4; tile++) {
        int j0 = tile * 64;
        float acc[4][8];
#pragma unroll
        for (int r4 = 0; r4 < 4; r4++)
#pragma unroll
            for (int r = 0; r < 8; r++) acc[r4][r] = 0.0f;

        for (int kh = 0; kh < 2; kh++) {
            int kb = kh * 128;
            // fill T[64][128] for this k-half
            for (int p = tid; p < 64 * 128; p += 256) {
                int lj = p >> 7, k = p & 127;
                T[lj * TROW + k] = preluf(g_cum[b][j0 + lj][kb + k] - cum_i[kb + k], a0);
            }
            __syncthreads();
            const float* T0 = &T[(jg * 4 + 0) * TROW];
            const float* T1 = &T[(jg * 4 + 1) * TROW];
            const float* T2 = &T[(jg * 4 + 2) * TROW];
            const float* T3 = &T[(jg * 4 + 3) * TROW];
#pragma unroll 2
            for (int k = 0; k < 128; k++) {
                float4 wA = W4[(kb + k) * 32 + oq * 2];
                float4 wB = W4[(kb + k) * 32 + oq * 2 + 1];
                float t0 = T0[k], t1 = T1[k], t2 = T2[k], t3 = T3[k];
                acc[0][0] = fmaf(t0, wA.x, acc[0][0]); acc[0][1] = fmaf(t0, wA.y, acc[0][1]);
                acc[0][2] = fmaf(t0, wA.z, acc[0][2]); acc[0][3] = fmaf(t0, wA.w, acc[0][3]);
                acc[0][4] = fmaf(t0, wB.x, acc[0][4]); acc[0][5] = fmaf(t0, wB.y, acc[0][5]);
                acc[0][6] = fmaf(t0, wB.z, acc[0][6]); acc[0][7] = fmaf(t0, wB.w, acc[0][7]);
                acc[1][0] = fmaf(t1, wA.x, acc[1][0]); acc[1][1] = fmaf(t1, wA.y, acc[1][1]);
                acc[1][2] = fmaf(t1, wA.z, acc[1][2]); acc[1][3] = fmaf(t1, wA.w, acc[1][3]);
                acc[1][4] = fmaf(t1, wB.x, acc[1][4]); acc[1][5] = fmaf(t1, wB.y, acc[1][5]);
                acc[1][6] = fmaf(t1, wB.z, acc[1][6]); acc[1][7] = fmaf(t1, wB.w, acc[1][7]);
                acc[2][0] = fmaf(t2, wA.x, acc[2][0]); acc[2][1] = fmaf(t2, wA.y, acc[2][1]);
                acc[2][2] = fmaf(t2, wA.z, acc[2][2]); acc[2][3] = fmaf(t2, wA.w, acc[2][3]);
                acc[2][4] = fmaf(t2, wB.x, acc[2][4]); acc[2][5] = fmaf(t2, wB.y, acc[2][5]);
                acc[2][6] = fmaf(t2, wB.z, acc[2][6]); acc[2][7] = fmaf(t2, wB.w, acc[2][7]);
                acc[3][0] = fmaf(t3, wA.x, acc[3][0]); acc[3][1] = fmaf(t3, wA.y, acc[3][1]);
                acc[3][2] = fmaf(t3, wA.z, acc[3][2]); acc[3][3] = fmaf(t3, wA.w, acc[3][3]);
                acc[3][4] = fmaf(t3, wB.x, acc[3][4]); acc[3][5] = fmaf(t3, wB.y, acc[3][5]);
                acc[3][6] = fmaf(t3, wB.z, acc[3][6]); acc[3][7] = fmaf(t3, wB.w, acc[3][7]);
            }
            __syncthreads();
        }
        // epilogue: 4 j's per thread
#pragma unroll
        for (int r4 = 0; r4 < 4; r4++) {
            int j = j0 + jg * 4 + r4;
            float part = 0.0f;
#pragma unroll
            for (int r = 0; r < 8; r++) {
                int o = oq * 8 + r;
                float h = acc[r4][r] + dt[r] + g_eterm[b][j][o];
                h = preluf(h, a1);
                part = fmaf(h, w2v[r], part);
            }
#pragma unroll
            for (int off = 8; off > 0; off >>= 1)
                part += __shfl_down_sync(0xffffffffu, part, off, 16);
            if (oq == 0) g_scores[b][i][j] = part + bs2v;
        }
    }
}

// ---------------- DP backpointers ----------------
__global__ void dp_k()
{
    int b = blockIdx.x, t = threadIdx.x; // 64 threads
    __shared__ float best[SS];
    __shared__ float rv[2];
    __shared__ int ri[2];
    for (int p = t; p < SS; p += 64) best[p] = 0.0f;
    if (t == 0) g_backptr[b][0] = 0;
    __syncthreads();
    for (int i = 1; i < SS; i++) {
        int start = (i > WSEG) ? (i - WSEG) : 0;
        int j = start + t;
        float v = (j < i) ? best[j] + g_scores[b][j][i] : -1000000000.0f;
        int idx = j;
#pragma unroll
        for (int off = 16; off > 0; off >>= 1) {
            float ov = __shfl_down_sync(0xffffffffu, v, off);
            int oi = __shfl_down_sync(0xffffffffu, idx, off);
            if (ov > v || (ov == v && oi < idx)) { v = ov; idx = oi; }
        }
        if ((t & 31) == 0) { rv[t >> 5] = v; ri[t >> 5] = idx; }
        __syncthreads();
        if (t == 0) {
            float v0 = rv[0], v1 = rv[1];
            int i0 = ri[0], i1 = ri[1];
            if (v1 > v0 || (v1 == v0 && i1 < i0)) { v0 = v1; i0 = i1; }
            best[i] = v0;
            g_backptr[b][i] = i0;
        }
        __syncthreads();
    }
}

// ---------------- backtrack + output bmask/pred_scores ----------------
__global__ void backtrack_k(const int* __restrict__ lengths, float* __restrict__ out)
{
    int t = threadIdx.x; // 256
    for (int p = t; p < BB * SS; p += 256) out[21504 + p] = 0.0f;
    __syncthreads();
    if (t < BB) {
        int b = t;
        int cur = lengths[b] - 1;
        float acc = 0.0f;
        for (int it = 0; it < SS; it++) {
            out[21504 + b * SS + cur] = 1.0f;
            int prev = g_backptr[b][cur];
            if (cur > 0) {
                acc += g_scores[b][prev][cur];
                cur = prev;
            } else {
                cur = 0;
            }
        }
        out[22016 + b] = acc;
    }
}

// ---------------- launch ----------------
extern "C" void kernel_launch(void* const* d_in, const int* in_sizes, int n_in,
                              void* d_out, int out_size)
{
    const float* x       = (const float*)d_in[0];
    const int*   lengths = (const int*)d_in[1];
    const float* wih0f = (const float*)d_in[2];
    const float* whh0f = (const float*)d_in[3];
    const float* bl0f  = (const float*)d_in[4];
    const float* wih0b = (const float*)d_in[5];
    const float* whh0b = (const float*)d_in[6];
    const float* bl0b  = (const float*)d_in[7];
    const float* wih1f = (const float*)d_in[8];
    const float* whh1f = (const float*)d_in[9];
    const float* bl1f  = (const float*)d_in[10];
    const float* wih1b = (const float*)d_in[11];
    const float* whh1b = (const float*)d_in[12];
    const float* bl1b  = (const float*)d_in[13];
    const float* a_s0 = (const float*)d_in[14];
    const float* w_s1 = (const float*)d_in[15];
    const float* b_s1 = (const float*)d_in[16];
    const float* a_s1 = (const float*)d_in[17];
    const float* w_s2 = (const float*)d_in[18];
    const float* b_s2 = (const float*)d_in[19];
    const float* a_c0 = (const float*)d_in[20];
    const float* w_c1 = (const float*)d_in[21];
    const float* b_c1 = (const float*)d_in[22];
    const float* a_c1 = (const float*)d_in[23];
    const float* w_c2 = (const float*)d_in[24];
    const float* b_c2 = (const float*)d_in[25];
    const float* a_b0 = (const float*)d_in[26];
    const float* w_b1 = (const float*)d_in[27];
    const float* b_b1 = (const float*)d_in[28];
    const float* a_b1 = (const float*)d_in[29];
    const float* w_b2 = (const float*)d_in[30];
    const float* b_b2 = (const float*)d_in[31];
    float* out = (float*)d_out;

    prep_k<<<512, 256>>>(wih0f, whh0f, wih0b, whh0b, wih1f, whh1f, wih1b, whh1b,
                         w_s1, w_c1, w_b1);

    inproj_k<INP><<<dim3(SS / 8, BB, 2), 512>>>(x, bl0f, bl0b, 0);
    recur_k<<<dim3(BB, 2), 256>>>(0);
    inproj_k<F2><<<dim3(SS / 8, BB, 2), 512>>>(x, bl1f, bl1b, 1);
    recur_k<<<dim3(BB, 2), 256>>>(1);

    cumsum_k<<<BB, F2>>>();
    determ_k<<<dim3(SS, BB), 128>>>(a_s0, b_s1);
    clsbin_k<<<dim3(SS, BB), 128>>>(a_c0, b_c1, a_c1, w_c2, b_c2,
                                    a_b0, b_b1, a_b1, w_b2, b_b2, out);
    scores_k<<<dim3(SS, BB), 256>>>(a_s0, a_s1, w_s2, b_s2);
    dp_k<<<BB, 64>>>();
    backtrack_k<<<1, 256>>>(lengths, out);
}

// round 5
// speedup vs baseline: 2.0549x; 2.0549x over previous
#include <cuda_runtime.h>
#include <math.h>
#include <stdint.h>

// Problem constants
#define BB   2
#define SS   256
#define INP  80
#define HID  128
#define F2   256
#define G4   512   // 4*HID
#define NCC  40
#define WSEG 64

// ---------------- device scratch (no allocation allowed) ----------------
__device__ float g_WihT0[2][INP][G4];    // [dir][i][g]
__device__ float g_WihT1[2][F2][G4];
__device__ float g_pre[2][BB][SS][G4];   // [dir][b][s][g]  (reused per layer)
__device__ float g_rnn[2][BB][SS][F2];   // [layer][b][s][f]
__device__ float g_cum[BB][SS][F2];
__device__ float g_WcT[F2][128];         // w_s1 c-part transposed, o padded 100->128 (zeros)
__device__ float g_WdT[F2][128];
__device__ float g_WeT[F2][128];
__device__ float g_wc1T[F2][80];
__device__ float g_wb1T[F2][80];
__device__ float g_dterm[BB][SS][128];   // prelu(rnn_i)@Wd^T + b_s1 (padded)
__device__ float g_eterm[BB][SS][128];   // prelu(rnn_j)@We^T
__device__ float g_scores[BB][SS][SS];   // scores[b][i][j], c = cum_j - cum_i
__device__ int   g_backptr[BB][SS];

__device__ __forceinline__ float sigf(float x) { return 1.0f / (1.0f + expf(-x)); }
__device__ __forceinline__ float preluf(float x, float a) { return x >= 0.0f ? x : a * x; }
// fast (MUFU ex2-based) activations for the recurrence critical path
__device__ __forceinline__ float sig_fast(float x) { return __fdividef(1.0f, 1.0f + __expf(-x)); }
__device__ __forceinline__ float tanh_fast(float x) { return __fdividef(2.0f, 1.0f + __expf(-2.0f * x)) - 1.0f; }

// ---------------- cluster / mbarrier helpers ----------------
__device__ __forceinline__ uint32_t ctarank() {
    uint32_t r; asm("mov.u32 %0, %%cluster_ctarank;" : "=r"(r)); return r;
}
__device__ __forceinline__ uint32_t mapa_u32(uint32_t addr, uint32_t rank) {
    uint32_t r; asm("mapa.shared::cluster.u32 %0, %1, %2;" : "=r"(r) : "r"(addr), "r"(rank));
    return r;
}
__device__ __forceinline__ void st_async_f32(uint32_t raddr, float v, uint32_t rmbar) {
    asm volatile("st.async.shared::cluster.mbarrier::complete_tx::bytes.b32 [%0], %1, [%2];"
                 :: "r"(raddr), "f"(v), "r"(rmbar) : "memory");
}
__device__ __forceinline__ void mbar_init(uint32_t mbar, uint32_t count) {
    asm volatile("mbarrier.init.shared.b64 [%0], %1;" :: "r"(mbar), "r"(count) : "memory");
}
__device__ __forceinline__ void mbar_expect_tx(uint32_t mbar, uint32_t tx) {
    asm volatile("mbarrier.arrive.expect_tx.shared.b64 _, [%0], %1;" :: "r"(mbar), "r"(tx) : "memory");
}
__device__ __forceinline__ void mbar_wait(uint32_t mbar, uint32_t parity) {
    asm volatile(
        "{\n\t.reg .pred P;\n\t"
        "WL_%=:\n\t"
        "mbarrier.try_wait.parity.acquire.cluster.shared::cta.b64 P, [%0], %1, 0x989680;\n\t"
        "@P bra.uni WD_%=;\n\t"
        "bra.uni WL_%=;\n\t"
        "WD_%=:\n\t}"
        :: "r"(mbar), "r"(parity) : "memory");
}
__device__ __forceinline__ void cluster_sync() {
    asm volatile("barrier.cluster.arrive.aligned;" ::: "memory");
    asm volatile("barrier.cluster.wait.aligned;" ::: "memory");
}

// ---------------- prep: transpose weights into friendly layouts ----------------
__global__ void prep_k(const float* __restrict__ wih0f,
                       const float* __restrict__ wih0b,
                       const float* __restrict__ wih1f,
                       const float* __restrict__ wih1b,
                       const float* __restrict__ ws1,  const float* __restrict__ wc1,
                       const float* __restrict__ wb1)
{
    int idx = blockIdx.x * blockDim.x + threadIdx.x;
    int n = gridDim.x * blockDim.x;
    for (int p = idx; p < 2 * INP * G4; p += n) {
        int d = p / (INP * G4), r = p % (INP * G4), i = r / G4, g = r % G4;
        g_WihT0[d][i][g] = (d ? wih0b : wih0f)[g * INP + i];
    }
    for (int p = idx; p < 2 * F2 * G4; p += n) {
        int d = p / (F2 * G4), r = p % (F2 * G4), i = r / G4, g = r % G4;
        g_WihT1[d][i][g] = (d ? wih1b : wih1f)[g * F2 + i];
    }
    for (int p = idx; p < F2 * 128; p += n) {
        int k = p / 128, o = p % 128;
        g_WcT[k][o] = (o < 100) ? ws1[o * 768 + k]        : 0.0f;
        g_WdT[k][o] = (o < 100) ? ws1[o * 768 + 256 + k]  : 0.0f;
        g_WeT[k][o] = (o < 100) ? ws1[o * 768 + 512 + k]  : 0.0f;
    }
    for (int p = idx; p < F2 * 80; p += n) {
        int k = p / 80, o = p % 80;
        g_wc1T[k][o] = wc1[o * F2 + k];
        g_wb1T[k][o] = wb1[o * F2 + k];
    }
}

// ---------------- input projection: pre = x @ Wih^T + b ----------------
template <int INDIM>
__global__ void inproj_k(const float* __restrict__ x0,
                         const float* __restrict__ bias_f, const float* __restrict__ bias_b,
                         int layer)
{
    int st = blockIdx.x * 8, b = blockIdx.y, d = blockIdx.z, g = threadIdx.x; // 512 threads
    __shared__ float xs[8][INDIM];
    const float* xin = layer ? &g_rnn[0][0][0][0] : x0;
    for (int p = g; p < 8 * INDIM; p += 512) {
        int ss = p / INDIM, i = p % INDIM;
        xs[ss][i] = xin[(b * SS + st + ss) * INDIM + i];
    }
    __syncthreads();
    const float* W = (INDIM == INP) ? &g_WihT0[d][0][0] : &g_WihT1[d][0][0];
    float bg = (d ? bias_b : bias_f)[g];
    float acc[8];
#pragma unroll
    for (int ss = 0; ss < 8; ss++) acc[ss] = bg;
    for (int i = 0; i < INDIM; i++) {
        float w = W[i * G4 + g];
#pragma unroll
        for (int ss = 0; ss < 8; ss++) acc[ss] = fmaf(xs[ss][i], w, acc[ss]);
    }
#pragma unroll
    for (int ss = 0; ss < 8; ss++) g_pre[d][b][st + ss][g] = acc[ss];
}

// ---------------- LSTM recurrence: 4-CTA cluster per (b, dir) chain ----------------
// rank r owns gate r (outputs [r*128, r*128+128)). Weights smem-resident.
// Per step: matvec from smem -> st.async 128 gate floats to rank0 -> rank0 LSTM cell
// -> st.async h broadcast to all 4 ranks.
// Dynamic smem layout (floats): [0,16896) Wsh[128][132]; [16896,17024) hs[128];
// [17024,17536) gates[512]; then 2 x u64 mbarriers (g_mbar, h_mbar).
#define WPAD 132
__global__ void __launch_bounds__(128) __cluster_dims__(4, 1, 1)
recur_k(const float* __restrict__ whh_f, const float* __restrict__ whh_b, int layer)
{
    extern __shared__ float sm[];
    float* Wsh   = sm;                 // [128][WPAD]
    float* hs    = sm + 128 * WPAD;    // [128]
    float* gates = hs + 128;           // [512]
    int t = threadIdx.x;
    uint32_t rank = ctarank();
    int chain = blockIdx.y;
    int b = chain >> 1, d = chain & 1;
    const float* __restrict__ whh = d ? whh_b : whh_f;

    uint32_t mb = (uint32_t)__cvta_generic_to_shared(gates + 512);
    uint32_t g_mbar = mb;          // on rank0: gate collection
    uint32_t h_mbar = mb + 8;      // on each rank: h delivery

    // load this rank's 128x128 weight slice (rows rank*128..+127 of w_hh, row-major)
    for (int p = t; p < 128 * 128; p += 128) {
        int row = p >> 7, k = p & 127;
        Wsh[row * WPAD + k] = whh[(rank * 128 + row) * 128 + k];
    }
    hs[t] = 0.0f;
    if (t == 0) { mbar_init(g_mbar, 1); mbar_init(h_mbar, 1); }
    __syncthreads();
    cluster_sync();  // peers' mbarriers initialized before any st.async

    // step-invariant remote addresses
    uint32_t gates_local = (uint32_t)__cvta_generic_to_shared(&gates[rank * 128 + t]);
    uint32_t g_slot_r0   = mapa_u32(gates_local, 0);
    uint32_t g_mbar_r0   = mapa_u32(g_mbar, 0);
    uint32_t hs_local    = (uint32_t)__cvta_generic_to_shared(&hs[t]);
    uint32_t h_slot[4], h_mbar_r[4];
#pragma unroll
    for (int r = 0; r < 4; r++) {
        h_slot[r]   = mapa_u32(hs_local, r);
        h_mbar_r[r] = mapa_u32(h_mbar, r);
    }

    const float* __restrict__ preB = &g_pre[d][b][0][0];
    float* __restrict__ outB = &g_rnn[layer][b][0][0];
    const float4* hs4 = (const float4*)hs;
    const float4* W4  = (const float4*)(Wsh + t * WPAD);  // byte offset t*528, 16B aligned
    float c = 0.0f;

    for (int step = 0; step < SS; ++step) {
        int s = d ? (SS - 1 - step) : step;
        if (t == 0) {
            mbar_expect_tx(h_mbar, 128 * 4);
            if (rank == 0) mbar_expect_tx(g_mbar, 512 * 4);
        }
        float accv[4];
        accv[0] = __ldg(&preB[s * G4 + rank * 128 + t]);
        accv[1] = 0.0f; accv[2] = 0.0f; accv[3] = 0.0f;
#pragma unroll
        for (int q = 0; q < 32; q++) {
            float4 w = W4[q];
            float4 h = hs4[q];
            float a = accv[q & 3];
            a = fmaf(h.x, w.x, a); a = fmaf(h.y, w.y, a);
            a = fmaf(h.z, w.z, a); a = fmaf(h.w, w.w, a);
            accv[q & 3] = a;
        }
        float gval = (accv[0] + accv[1]) + (accv[2] + accv[3]);
        st_async_f32(g_slot_r0, gval, g_mbar_r0);

        if (rank == 0) {
            mbar_wait(g_mbar, step & 1);
            float gi = gates[t], gf = gates[128 + t], gG = gates[256 + t], go = gates[384 + t];
            c = sig_fast(gf) * c + sig_fast(gi) * tanh_fast(gG);
            float h = sig_fast(go) * tanh_fast(c);
            outB[s * F2 + d * HID + t] = h;
#pragma unroll
            for (int r = 0; r < 4; r++) st_async_f32(h_slot[r], h, h_mbar_r[r]);
        }
        mbar_wait(h_mbar, step & 1);
    }
    cluster_sync();
}

// ---------------- cumsum over time ----------------
__global__ void cumsum_k()
{
    int b = blockIdx.x, k = threadIdx.x; // 256
    float run = 0.0f;
#pragma unroll 4
    for (int s = 0; s < SS; s++) {
        run += g_rnn[1][b][s][k];
        g_cum[b][s][k] = run;
    }
}

// ---------------- dterm/eterm precompute ----------------
__global__ void determ_k(const float* __restrict__ a_s0p, const float* __restrict__ bs1)
{
    int s = blockIdx.x, b = blockIdx.y, t = threadIdx.x; // 128
    __shared__ float pr[F2];
    float a0 = *a_s0p;
    for (int p = t; p < F2; p += 128) pr[p] = preluf(g_rnn[1][b][s][p], a0);
    __syncthreads();
    float ad = 0.0f, ae = 0.0f;
    for (int k = 0; k < F2; k++) {
        float p = pr[k];
        ad = fmaf(p, g_WdT[k][t], ad);
        ae = fmaf(p, g_WeT[k][t], ae);
    }
    g_dterm[b][s][t] = ad + ((t < 100) ? bs1[t] : 0.0f);
    g_eterm[b][s][t] = ae;
}

// ---------------- cls / bin MLPs ----------------
__global__ void clsbin_k(const float* __restrict__ ac0, const float* __restrict__ bc1,
                         const float* __restrict__ ac1, const float* __restrict__ wc2,
                         const float* __restrict__ bc2,
                         const float* __restrict__ ab0, const float* __restrict__ bb1,
                         const float* __restrict__ ab1, const float* __restrict__ wb2,
                         const float* __restrict__ bb2, float* __restrict__ out)
{
    int s = blockIdx.x, b = blockIdx.y, t = threadIdx.x; // 128
    __shared__ float pr[F2];
    __shared__ float h1[80];
    // CLS
    float a = *ac0;
    for (int p = t; p < F2; p += 128) pr[p] = preluf(g_rnn[1][b][s][p], a);
    __syncthreads();
    if (t < 80) {
        float acc = bc1[t];
        for (int k = 0; k < F2; k++) acc = fmaf(pr[k], g_wc1T[k][t], acc);
        h1[t] = preluf(acc, *ac1);
    }
    __syncthreads();
    if (t < NCC) {
        float acc = bc2[t];
        for (int q = 0; q < 80; q++) acc = fmaf(h1[q], wc2[t * 80 + q], acc);
        out[(b * SS + s) * NCC + t] = acc;
    }
    __syncthreads();
    // BIN
    a = *ab0;
    for (int p = t; p < F2; p += 128) pr[p] = preluf(g_rnn[1][b][s][p], a);
    __syncthreads();
    if (t < 80) {
        float acc = bb1[t];
        for (int k = 0; k < F2; k++) acc = fmaf(pr[k], g_wb1T[k][t], acc);
        h1[t] = preluf(acc, *ab1);
    }
    __syncthreads();
    if (t < 2) {
        float acc = bb2[t];
        for (int q = 0; q < 80; q++) acc = fmaf(h1[q], wb2[t * 80 + q], acc);
        out[20480 + (b * SS + s) * 2 + t] = acc;
    }
}

// ---------------- pairwise scores: block = (i, b), 256 threads ----------------
#define TROW 132   // 128 k-half + 4 pad (bank-shift 4/row)
__global__ void __launch_bounds__(256) scores_k(const float* __restrict__ a_s0p,
                         const float* __restrict__ a_s1p,
                         const float* __restrict__ ws2, const float* __restrict__ bs2)
{
    int i = blockIdx.x, b = blockIdx.y, tid = threadIdx.x;
    int oq = tid & 15, jg = tid >> 4;   // 16 output-groups x 16 j-groups(4 j)
    __shared__ float cum_i[F2];
    __shared__ float T[64 * TROW];
    float a0 = *a_s0p, a1 = *a_s1p;
    for (int p = tid; p < F2; p += 256) cum_i[p] = g_cum[b][i][p];
    float dt[8], w2v[8];
#pragma unroll
    for (int r = 0; r < 8; r++) {
        int o = oq * 8 + r;
        dt[r] = g_dterm[b][i][o];
        w2v[r] = (o < 100) ? ws2[o] : 0.0f;
    }
    float bs2v = bs2[0];
    __syncthreads();
    const float4* __restrict__ W4 = reinterpret_cast<const float4*>(&g_WcT[0][0]);
    for (int tile = 0; tile < 4; tile++) {
        int j0 = tile * 64;
        float acc[4][8];
#pragma unroll
        for (int r4 = 0; r4 < 4; r4++)
#pragma unroll
            for (int r = 0; r < 8; r++) acc[r4][r] = 0.0f;

        for (int kh = 0; kh < 2; kh++) {
            int kb = kh * 128;
            for (int p = tid; p < 64 * 128; p += 256) {
                int lj = p >> 7, k = p & 127;
                T[lj * TROW + k] = preluf(g_cum[b][j0 + lj][kb + k] - cum_i[kb + k], a0);
            }
            __syncthreads();
            const float* T0 = &T[(jg * 4 + 0) * TROW];
            const float* T1 = &T[(jg * 4 + 1) * TROW];
            const float* T2 = &T[(jg * 4 + 2) * TROW];
            const float* T3 = &T[(jg * 4 + 3) * TROW];
#pragma unroll 2
            for (int k = 0; k < 128; k++) {
                float4 wA = W4[(kb + k) * 32 + oq * 2];
                float4 wB = W4[(kb + k) * 32 + oq * 2 + 1];
                float t0 = T0[k], t1 = T1[k], t2 = T2[k], t3 = T3[k];
                acc[0][0] = fmaf(t0, wA.x, acc[0][0]); acc[0][1] = fmaf(t0, wA.y, acc[0][1]);
                acc[0][2] = fmaf(t0, wA.z, acc[0][2]); acc[0][3] = fmaf(t0, wA.w, acc[0][3]);
                acc[0][4] = fmaf(t0, wB.x, acc[0][4]); acc[0][5] = fmaf(t0, wB.y, acc[0][5]);
                acc[0][6] = fmaf(t0, wB.z, acc[0][6]); acc[0][7] = fmaf(t0, wB.w, acc[0][7]);
                acc[1][0] = fmaf(t1, wA.x, acc[1][0]); acc[1][1] = fmaf(t1, wA.y, acc[1][1]);
                acc[1][2] = fmaf(t1, wA.z, acc[1][2]); acc[1][3] = fmaf(t1, wA.w, acc[1][3]);
                acc[1][4] = fmaf(t1, wB.x, acc[1][4]); acc[1][5] = fmaf(t1, wB.y, acc[1][5]);
                acc[1][6] = fmaf(t1, wB.z, acc[1][6]); acc[1][7] = fmaf(t1, wB.w, acc[1][7]);
                acc[2][0] = fmaf(t2, wA.x, acc[2][0]); acc[2][1] = fmaf(t2, wA.y, acc[2][1]);
                acc[2][2] = fmaf(t2, wA.z, acc[2][2]); acc[2][3] = fmaf(t2, wA.w, acc[2][3]);
                acc[2][4] = fmaf(t2, wB.x, acc[2][4]); acc[2][5] = fmaf(t2, wB.y, acc[2][5]);
                acc[2][6] = fmaf(t2, wB.z, acc[2][6]); acc[2][7] = fmaf(t2, wB.w, acc[2][7]);
                acc[3][0] = fmaf(t3, wA.x, acc[3][0]); acc[3][1] = fmaf(t3, wA.y, acc[3][1]);
                acc[3][2] = fmaf(t3, wA.z, acc[3][2]); acc[3][3] = fmaf(t3, wA.w, acc[3][3]);
                acc[3][4] = fmaf(t3, wB.x, acc[3][4]); acc[3][5] = fmaf(t3, wB.y, acc[3][5]);
                acc[3][6] = fmaf(t3, wB.z, acc[3][6]); acc[3][7] = fmaf(t3, wB.w, acc[3][7]);
            }
            __syncthreads();
        }
#pragma unroll
        for (int r4 = 0; r4 < 4; r4++) {
            int j = j0 + jg * 4 + r4;
            float part = 0.0f;
#pragma unroll
            for (int r = 0; r < 8; r++) {
                int o = oq * 8 + r;
                float h = acc[r4][r] + dt[r] + g_eterm[b][j][o];
                h = preluf(h, a1);
                part = fmaf(h, w2v[r], part);
            }
#pragma unroll
            for (int off = 8; off > 0; off >>= 1)
                part += __shfl_down_sync(0xffffffffu, part, off, 16);
            if (oq == 0) g_scores[b][i][j] = part + bs2v;
        }
    }
}

// ---------------- DP backpointers ----------------
__global__ void dp_k()
{
    int b = blockIdx.x, t = threadIdx.x; // 64 threads
    __shared__ float best[SS];
    __shared__ float rv[2];
    __shared__ int ri[2];
    for (int p = t; p < SS; p += 64) best[p] = 0.0f;
    if (t == 0) g_backptr[b][0] = 0;
    __syncthreads();
    for (int i = 1; i < SS; i++) {
        int start = (i > WSEG) ? (i - WSEG) : 0;
        int j = start + t;
        float v = (j < i) ? best[j] + g_scores[b][j][i] : -1000000000.0f;
        int idx = j;
#pragma unroll
        for (int off = 16; off > 0; off >>= 1) {
            float ov = __shfl_down_sync(0xffffffffu, v, off);
            int oi = __shfl_down_sync(0xffffffffu, idx, off);
            if (ov > v || (ov == v && oi < idx)) { v = ov; idx = oi; }
        }
        if ((t & 31) == 0) { rv[t >> 5] = v; ri[t >> 5] = idx; }
        __syncthreads();
        if (t == 0) {
            float v0 = rv[0], v1 = rv[1];
            int i0 = ri[0], i1 = ri[1];
            if (v1 > v0 || (v1 == v0 && i1 < i0)) { v0 = v1; i0 = i1; }
            best[i] = v0;
            g_backptr[b][i] = i0;
        }
        __syncthreads();
    }
}

// ---------------- backtrack + output bmask/pred_scores ----------------
__global__ void backtrack_k(const int* __restrict__ lengths, float* __restrict__ out)
{
    int t = threadIdx.x; // 256
    for (int p = t; p < BB * SS; p += 256) out[21504 + p] = 0.0f;
    __syncthreads();
    if (t < BB) {
        int b = t;
        int cur = lengths[b] - 1;
        float acc = 0.0f;
        for (int it = 0; it < SS; it++) {
            out[21504 + b * SS + cur] = 1.0f;
            int prev = g_backptr[b][cur];
            if (cur > 0) {
                acc += g_scores[b][prev][cur];
                cur = prev;
            } else {
                cur = 0;
            }
        }
        out[22016 + b] = acc;
    }
}

// ---------------- launch ----------------
extern "C" void kernel_launch(void* const* d_in, const int* in_sizes, int n_in,
                              void* d_out, int out_size)
{
    const float* x       = (const float*)d_in[0];
    const int*   lengths = (const int*)d_in[1];
    const float* wih0f = (const float*)d_in[2];
    const float* whh0f = (const float*)d_in[3];
    const float* bl0f  = (const float*)d_in[4];
    const float* wih0b = (const float*)d_in[5];
    const float* whh0b = (const float*)d_in[6];
    const float* bl0b  = (const float*)d_in[7];
    const float* wih1f = (const float*)d_in[8];
    const float* whh1f = (const float*)d_in[9];
    const float* bl1f  = (const float*)d_in[10];
    const float* wih1b = (const float*)d_in[11];
    const float* whh1b = (const float*)d_in[12];
    const float* bl1b  = (const float*)d_in[13];
    const float* a_s0 = (const float*)d_in[14];
    const float* w_s1 = (const float*)d_in[15];
    const float* b_s1 = (const float*)d_in[16];
    const float* a_s1 = (const float*)d_in[17];
    const float* w_s2 = (const float*)d_in[18];
    const float* b_s2 = (const float*)d_in[19];
    const float* a_c0 = (const float*)d_in[20];
    const float* w_c1 = (const float*)d_in[21];
    const float* b_c1 = (const float*)d_in[22];
    const float* a_c1 = (const float*)d_in[23];
    const float* w_c2 = (const float*)d_in[24];
    const float* b_c2 = (const float*)d_in[25];
    const float* a_b0 = (const float*)d_in[26];
    const float* w_b1 = (const float*)d_in[27];
    const float* b_b1 = (const float*)d_in[28];
    const float* a_b1 = (const float*)d_in[29];
    const float* w_b2 = (const float*)d_in[30];
    const float* b_b2 = (const float*)d_in[31];
    float* out = (float*)d_out;

    const int RECUR_SMEM = (128 * WPAD + 128 + 512) * 4 + 64;  // ~70.2 KB
    cudaFuncSetAttribute(recur_k, cudaFuncAttributeMaxDynamicSharedMemorySize, RECUR_SMEM);

    prep_k<<<512, 256>>>(wih0f, wih0b, wih1f, wih1b, w_s1, w_c1, w_b1);

    inproj_k<INP><<<dim3(SS / 8, BB, 2), 512>>>(x, bl0f, bl0b, 0);
    recur_k<<<dim3(4, 4), 128, RECUR_SMEM>>>(whh0f, whh0b, 0);
    inproj_k<F2><<<dim3(SS / 8, BB, 2), 512>>>(x, bl1f, bl1b, 1);
    recur_k<<<dim3(4, 4), 128, RECUR_SMEM>>>(whh1f, whh1b, 1);

    cumsum_k<<<BB, F2>>>();
    determ_k<<<dim3(SS, BB), 128>>>(a_s0, b_s1);
    clsbin_k<<<dim3(SS, BB), 128>>>(a_c0, b_c1, a_c1, w_c2, b_c2,
                                    a_b0, b_b1, a_b1, w_b2, b_b2, out);
    scores_k<<<dim3(SS, BB), 256>>>(a_s0, a_s1, w_s2, b_s2);
    dp_k<<<BB, 64>>>();
    backtrack_k<<<1, 256>>>(lengths, out);
}

// round 6
// speedup vs baseline: 2.6387x; 1.2841x over previous
#include <cuda_runtime.h>
#include <math.h>
#include <stdint.h>

// Problem constants
#define BB   2
#define SS   256
#define INP  80
#define HID  128
#define F2   256
#define G4   512   // 4*HID
#define NCC  40
#define WSEG 64

typedef unsigned long long u64;

// ---------------- device scratch (no allocation allowed) ----------------
__device__ float g_WihT0[2][INP][G4];    // [dir][i][g]
__device__ float g_WihT1[2][F2][G4];
__device__ float g_pre[2][BB][SS][G4];   // [dir][b][s][g]  (reused per layer)
__device__ float g_rnn[2][BB][SS][F2];   // [layer][b][s][f]
__device__ float g_cum[BB][SS][F2];
__device__ float g_WcT[F2][128];         // w_s1 c-part transposed, o padded 100->128 (zeros)
__device__ float g_WdT[F2][128];
__device__ float g_WeT[F2][128];
__device__ float g_wc1T[F2][80];
__device__ float g_wb1T[F2][80];
__device__ float g_dterm[BB][SS][128];   // prelu(rnn_i)@Wd^T + b_s1 (padded)
__device__ float g_eterm[BB][SS][128];   // prelu(rnn_j)@We^T
__device__ float g_scores[BB][SS][SS];   // scores[b][i][j]
__device__ float g_scoresT[BB][SS][SS];  // transposed copy for DP column reads
__device__ int   g_backptr[BB][SS];

__device__ __forceinline__ float sigf(float x) { return 1.0f / (1.0f + expf(-x)); }
__device__ __forceinline__ float preluf(float x, float a) { return x >= 0.0f ? x : a * x; }
__device__ __forceinline__ float sig_fast(float x) { return __fdividef(1.0f, 1.0f + __expf(-x)); }
__device__ __forceinline__ float tanh_fast(float x) { return __fdividef(2.0f, 1.0f + __expf(-2.0f * x)) - 1.0f; }

// ---------------- f32x2 packed math helpers ----------------
__device__ __forceinline__ void fma2(u64& acc, u64 a, u64 b) {
    asm("fma.rn.f32x2 %0, %1, %2, %0;" : "+l"(acc) : "l"(a), "l"(b));
}
__device__ __forceinline__ u64 packf2(float lo, float hi) {
    u64 r; asm("mov.b64 %0, {%1, %2};" : "=l"(r) : "f"(lo), "f"(hi)); return r;
}
__device__ __forceinline__ float2 unpackf2(u64 v) {
    float2 r; asm("mov.b64 {%0, %1}, %2;" : "=f"(r.x), "=f"(r.y) : "l"(v)); return r;
}

// ---------------- cluster / mbarrier helpers ----------------
__device__ __forceinline__ uint32_t ctarank() {
    uint32_t r; asm("mov.u32 %0, %%cluster_ctarank;" : "=r"(r)); return r;
}
__device__ __forceinline__ uint32_t mapa_u32(uint32_t addr, uint32_t rank) {
    uint32_t r; asm("mapa.shared::cluster.u32 %0, %1, %2;" : "=r"(r) : "r"(addr), "r"(rank));
    return r;
}
__device__ __forceinline__ void st_async_f32(uint32_t raddr, float v, uint32_t rmbar) {
    asm volatile("st.async.shared::cluster.mbarrier::complete_tx::bytes.b32 [%0], %1, [%2];"
                 :: "r"(raddr), "f"(v), "r"(rmbar) : "memory");
}
__device__ __forceinline__ void mbar_init(uint32_t mbar, uint32_t count) {
    asm volatile("mbarrier.init.shared.b64 [%0], %1;" :: "r"(mbar), "r"(count) : "memory");
}
__device__ __forceinline__ void mbar_expect_tx(uint32_t mbar, uint32_t tx) {
    asm volatile("mbarrier.arrive.expect_tx.shared.b64 _, [%0], %1;" :: "r"(mbar), "r"(tx) : "memory");
}
__device__ __forceinline__ void mbar_wait(uint32_t mbar, uint32_t parity) {
    asm volatile(
        "{\n\t.reg .pred P;\n\t"
        "WL_%=:\n\t"
        "mbarrier.try_wait.parity.acquire.cluster.shared::cta.b64 P, [%0], %1, 0x989680;\n\t"
        "@P bra.uni WD_%=;\n\t"
        "bra.uni WL_%=;\n\t"
        "WD_%=:\n\t}"
        :: "r"(mbar), "r"(parity) : "memory");
}
__device__ __forceinline__ void cluster_sync() {
    asm volatile("barrier.cluster.arrive.aligned;" ::: "memory");
    asm volatile("barrier.cluster.wait.aligned;" ::: "memory");
}

// ---------------- prep: transpose weights into friendly layouts ----------------
__global__ void prep_k(const float* __restrict__ wih0f,
                       const float* __restrict__ wih0b,
                       const float* __restrict__ wih1f,
                       const float* __restrict__ wih1b,
                       const float* __restrict__ ws1,  const float* __restrict__ wc1,
                       const float* __restrict__ wb1)
{
    int idx = blockIdx.x * blockDim.x + threadIdx.x;
    int n = gridDim.x * blockDim.x;
    for (int p = idx; p < 2 * INP * G4; p += n) {
        int d = p / (INP * G4), r = p % (INP * G4), i = r / G4, g = r % G4;
        g_WihT0[d][i][g] = (d ? wih0b : wih0f)[g * INP + i];
    }
    for (int p = idx; p < 2 * F2 * G4; p += n) {
        int d = p / (F2 * G4), r = p % (F2 * G4), i = r / G4, g = r % G4;
        g_WihT1[d][i][g] = (d ? wih1b : wih1f)[g * F2 + i];
    }
    for (int p = idx; p < F2 * 128; p += n) {
        int k = p / 128, o = p % 128;
        g_WcT[k][o] = (o < 100) ? ws1[o * 768 + k]        : 0.0f;
        g_WdT[k][o] = (o < 100) ? ws1[o * 768 + 256 + k]  : 0.0f;
        g_WeT[k][o] = (o < 100) ? ws1[o * 768 + 512 + k]  : 0.0f;
    }
    for (int p = idx; p < F2 * 80; p += n) {
        int k = p / 80, o = p % 80;
        g_wc1T[k][o] = wc1[o * F2 + k];
        g_wb1T[k][o] = wb1[o * F2 + k];
    }
}

// ---------------- input projection: pre = x @ Wih^T + b ----------------
template <int INDIM>
__global__ void inproj_k(const float* __restrict__ x0,
                         const float* __restrict__ bias_f, const float* __restrict__ bias_b,
                         int layer)
{
    int st = blockIdx.x * 8, b = blockIdx.y, d = blockIdx.z, g = threadIdx.x; // 512 threads
    __shared__ float xs[8][INDIM];
    const float* xin = layer ? &g_rnn[0][0][0][0] : x0;
    for (int p = g; p < 8 * INDIM; p += 512) {
        int ss = p / INDIM, i = p % INDIM;
        xs[ss][i] = xin[(b * SS + st + ss) * INDIM + i];
    }
    __syncthreads();
    const float* W = (INDIM == INP) ? &g_WihT0[d][0][0] : &g_WihT1[d][0][0];
    float bg = (d ? bias_b : bias_f)[g];
    float acc[8];
#pragma unroll
    for (int ss = 0; ss < 8; ss++) acc[ss] = bg;
    for (int i = 0; i < INDIM; i += 4) {   // unroll-4: MLP=4 on W stream
        float w0 = W[(i + 0) * G4 + g];
        float w1 = W[(i + 1) * G4 + g];
        float w2 = W[(i + 2) * G4 + g];
        float w3 = W[(i + 3) * G4 + g];
#pragma unroll
        for (int ss = 0; ss < 8; ss++) {
            float a = acc[ss];
            a = fmaf(xs[ss][i + 0], w0, a);
            a = fmaf(xs[ss][i + 1], w1, a);
            a = fmaf(xs[ss][i + 2], w2, a);
            a = fmaf(xs[ss][i + 3], w3, a);
            acc[ss] = a;
        }
    }
#pragma unroll
    for (int ss = 0; ss < 8; ss++) g_pre[d][b][st + ss][g] = acc[ss];
}

// ---------------- LSTM recurrence: 4-CTA cluster, register weights, one-hop ----------------
// 256 threads: thread t -> output o=t>>1 (of this rank's gate), k-half = t&1 (64 k each).
// Weights live in 32 f32x2 registers per thread. Per step: matvec -> even lanes
// st.async gate value to ALL 4 ranks (double-buffered gates, tx-mbarrier) ->
// every rank redundantly computes the LSTM cell (c replicated, deterministic) ->
// h written to LOCAL smem only. One DSMEM hop per step.
__global__ void __launch_bounds__(256) __cluster_dims__(4, 1, 1)
recur_k(const float* __restrict__ whh_f, const float* __restrict__ whh_b, int layer)
{
    __shared__ float hs[HID];
    __shared__ float gbuf[2][G4];
    __shared__ alignas(8) u64 mbar[1];
    int t = threadIdx.x;
    uint32_t rank = ctarank();
    int chain = blockIdx.y;
    int b = chain >> 1, d = chain & 1;
    const float* __restrict__ whh = d ? whh_b : whh_f;
    int o = t >> 1, half = t & 1;

    // load my 64 weights (k-half of row rank*128+o) as 32 packed f32x2 regs
    u64 wreg[32];
    {
        const ulonglong2* wrow = reinterpret_cast<const ulonglong2*>(
            whh + (rank * 128 + o) * 128 + half * 64);
#pragma unroll
        for (int q = 0; q < 16; q++) { ulonglong2 u = wrow[q]; wreg[2 * q] = u.x; wreg[2 * q + 1] = u.y; }
    }

    if (t < HID) hs[t] = 0.0f;
    uint32_t mb = (uint32_t)__cvta_generic_to_shared(mbar);
    if (t == 0) mbar_init(mb, 1);
    __syncthreads();
    cluster_sync();   // peers' mbarriers ready before any st.async

    // remote slots for my gate value (buffer 0); buffer 1 is +2048 bytes
    uint32_t slot0[4], mbar_r[4];
    {
        uint32_t loc = (uint32_t)__cvta_generic_to_shared(&gbuf[0][rank * 128 + o]);
#pragma unroll
        for (int r = 0; r < 4; r++) {
            slot0[r]  = mapa_u32(loc, r);
            mbar_r[r] = mapa_u32(mb, r);
        }
    }

    const float* __restrict__ preB = &g_pre[d][b][0][0];
    float* __restrict__ outB = &g_rnn[layer][b][0][0];
    const ulonglong2* hs2 = reinterpret_cast<const ulonglong2*>(hs);
    float c = 0.0f;

    for (int step = 0; step < SS; ++step) {
        int s = d ? (SS - 1 - step) : step;
        float pre = __ldg(&preB[s * G4 + rank * 128 + o]);
        if (t == 0) mbar_expect_tx(mb, G4 * 4);   // 512 floats arrive per phase

        // matvec over my 64-k half, weights in regs, h from local smem
        u64 a0 = 0, a1 = 0, a2 = 0, a3 = 0;
        const ulonglong2* hp = hs2 + half * 16;   // 16 x 16B = 64 floats
#pragma unroll
        for (int q = 0; q < 16; q++) {
            ulonglong2 h = hp[q];
            if (q & 1) { fma2(a2, wreg[2 * q], h.x); fma2(a3, wreg[2 * q + 1], h.y); }
            else       { fma2(a0, wreg[2 * q], h.x); fma2(a1, wreg[2 * q + 1], h.y); }
        }
        float2 f0 = unpackf2(a0), f1 = unpackf2(a1), f2 = unpackf2(a2), f3 = unpackf2(a3);
        float part = ((f0.x + f0.y) + (f1.x + f1.y)) + ((f2.x + f2.y) + (f3.x + f3.y));
        part += __shfl_xor_sync(0xffffffffu, part, 1);
        if (half == 0) {
            float gval = part + pre;
            uint32_t boff = (step & 1) ? (uint32_t)(G4 * 4) : 0u;
#pragma unroll
            for (int r = 0; r < 4; r++) st_async_f32(slot0[r] + boff, gval, mbar_r[r]);
        }
        mbar_wait(mb, step & 1);
        if (t < HID) {
            const float* gb = gbuf[step & 1];
            float gi = gb[t], gf = gb[HID + t], gg = gb[2 * HID + t], go = gb[3 * HID + t];
            c = sig_fast(gf) * c + sig_fast(gi) * tanh_fast(gg);
            float h = sig_fast(go) * tanh_fast(c);
            hs[t] = h;
            if (rank == 0) outB[s * F2 + d * HID + t] = h;
        }
        __syncthreads();   // order hs write vs next matvec read
    }
    cluster_sync();
}

// ---------------- cumsum over time ----------------
__global__ void cumsum_k()
{
    int b = blockIdx.x, k = threadIdx.x; // 256
    float run = 0.0f;
#pragma unroll 4
    for (int s = 0; s < SS; s++) {
        run += g_rnn[1][b][s][k];
        g_cum[b][s][k] = run;
    }
}

// ---------------- dterm/eterm precompute ----------------
__global__ void determ_k(const float* __restrict__ a_s0p, const float* __restrict__ bs1)
{
    int s = blockIdx.x, b = blockIdx.y, t = threadIdx.x; // 128
    __shared__ float pr[F2];
    float a0 = *a_s0p;
    for (int p = t; p < F2; p += 128) pr[p] = preluf(g_rnn[1][b][s][p], a0);
    __syncthreads();
    float ad = 0.0f, ae = 0.0f;
    for (int k = 0; k < F2; k++) {
        float p = pr[k];
        ad = fmaf(p, g_WdT[k][t], ad);
        ae = fmaf(p, g_WeT[k][t], ae);
    }
    g_dterm[b][s][t] = ad + ((t < 100) ? bs1[t] : 0.0f);
    g_eterm[b][s][t] = ae;
}

// ---------------- cls / bin MLPs ----------------
__global__ void clsbin_k(const float* __restrict__ ac0, const float* __restrict__ bc1,
                         const float* __restrict__ ac1, const float* __restrict__ wc2,
                         const float* __restrict__ bc2,
                         const float* __restrict__ ab0, const float* __restrict__ bb1,
                         const float* __restrict__ ab1, const float* __restrict__ wb2,
                         const float* __restrict__ bb2, float* __restrict__ out)
{
    int s = blockIdx.x, b = blockIdx.y, t = threadIdx.x; // 128
    __shared__ float pr[F2];
    __shared__ float h1[80];
    float a = *ac0;
    for (int p = t; p < F2; p += 128) pr[p] = preluf(g_rnn[1][b][s][p], a);
    __syncthreads();
    if (t < 80) {
        float acc = bc1[t];
        for (int k = 0; k < F2; k++) acc = fmaf(pr[k], g_wc1T[k][t], acc);
        h1[t] = preluf(acc, *ac1);
    }
    __syncthreads();
    if (t < NCC) {
        float acc = bc2[t];
        for (int q = 0; q < 80; q++) acc = fmaf(h1[q], wc2[t * 80 + q], acc);
        out[(b * SS + s) * NCC + t] = acc;
    }
    __syncthreads();
    a = *ab0;
    for (int p = t; p < F2; p += 128) pr[p] = preluf(g_rnn[1][b][s][p], a);
    __syncthreads();
    if (t < 80) {
        float acc = bb1[t];
        for (int k = 0; k < F2; k++) acc = fmaf(pr[k], g_wb1T[k][t], acc);
        h1[t] = preluf(acc, *ab1);
    }
    __syncthreads();
    if (t < 2) {
        float acc = bb2[t];
        for (int q = 0; q < 80; q++) acc = fmaf(h1[q], wb2[t * 80 + q], acc);
        out[20480 + (b * SS + s) * 2 + t] = acc;
    }
}

// ---------------- pairwise scores: f32x2 packed, block=(i,b), 256 threads ----------------
// T values duplicated into both f32x2 lanes at fill time (u64 smem tile),
// W loaded as output-pair u64s -> inner loop is 16 fma.rn.f32x2 per k.
#define T2ROW 130
__global__ void __launch_bounds__(256) scores_k(const float* __restrict__ a_s0p,
                         const float* __restrict__ a_s1p,
                         const float* __restrict__ ws2, const float* __restrict__ bs2)
{
    extern __shared__ float smd[];
    float* cum_i = smd;                                  // 256 floats
    u64* T2 = reinterpret_cast<u64*>(smd + 256);         // [64][T2ROW]
    int i = blockIdx.x, b = blockIdx.y, tid = threadIdx.x;
    int oq = tid & 15, jg = tid >> 4;   // 16 output-groups x 16 j-groups (4 j each)
    float a0 = *a_s0p, a1 = *a_s1p;
    for (int p = tid; p < F2; p += 256) cum_i[p] = g_cum[b][i][p];
    float dt[8], w2v[8];
#pragma unroll
    for (int r = 0; r < 8; r++) {
        int o = oq * 8 + r;
        dt[r] = g_dterm[b][i][o];
        w2v[r] = (o < 100) ? ws2[o] : 0.0f;
    }
    float bs2v = bs2[0];
    __syncthreads();
    const ulonglong2* __restrict__ W2 = reinterpret_cast<const ulonglong2*>(&g_WcT[0][0]);
    for (int tile = 0; tile < 4; tile++) {
        int j0 = tile * 64;
        u64 acc[4][4];
#pragma unroll
        for (int r4 = 0; r4 < 4; r4++)
#pragma unroll
            for (int p2 = 0; p2 < 4; p2++) acc[r4][p2] = 0ull;

        for (int kh = 0; kh < 2; kh++) {
            int kb = kh * 128;
            for (int p = tid; p < 64 * 128; p += 256) {
                int lj = p >> 7, k = p & 127;
                float v = preluf(g_cum[b][j0 + lj][kb + k] - cum_i[kb + k], a0);
                T2[lj * T2ROW + k] = packf2(v, v);
            }
            __syncthreads();
            const u64* Ta = &T2[(jg * 4 + 0) * T2ROW];
            const u64* Tb = &T2[(jg * 4 + 1) * T2ROW];
            const u64* Tc = &T2[(jg * 4 + 2) * T2ROW];
            const u64* Td = &T2[(jg * 4 + 3) * T2ROW];
#pragma unroll 2
            for (int k = 0; k < 128; k++) {
                ulonglong2 wA = W2[(kb + k) * 32 + 2 * oq];
                ulonglong2 wB = W2[(kb + k) * 32 + 2 * oq + 1];
                u64 t0 = Ta[k], t1 = Tb[k], t2 = Tc[k], t3 = Td[k];
                fma2(acc[0][0], t0, wA.x); fma2(acc[0][1], t0, wA.y);
                fma2(acc[0][2], t0, wB.x); fma2(acc[0][3], t0, wB.y);
                fma2(acc[1][0], t1, wA.x); fma2(acc[1][1], t1, wA.y);
                fma2(acc[1][2], t1, wB.x); fma2(acc[1][3], t1, wB.y);
                fma2(acc[2][0], t2, wA.x); fma2(acc[2][1], t2, wA.y);
                fma2(acc[2][2], t2, wB.x); fma2(acc[2][3], t2, wB.y);
                fma2(acc[3][0], t3, wA.x); fma2(acc[3][1], t3, wA.y);
                fma2(acc[3][2], t3, wB.x); fma2(acc[3][3], t3, wB.y);
            }
            __syncthreads();
        }
#pragma unroll
        for (int r4 = 0; r4 < 4; r4++) {
            int j = j0 + jg * 4 + r4;
            float part = 0.0f;
#pragma unroll
            for (int p2 = 0; p2 < 4; p2++) {
                float2 f = unpackf2(acc[r4][p2]);
                int r = 2 * p2, o = oq * 8 + r;
                float h0 = f.x + dt[r]     + g_eterm[b][j][o];
                float h1 = f.y + dt[r + 1] + g_eterm[b][j][o + 1];
                part = fmaf(preluf(h0, a1), w2v[r],     part);
                part = fmaf(preluf(h1, a1), w2v[r + 1], part);
            }
#pragma unroll
            for (int off = 8; off > 0; off >>= 1)
                part += __shfl_down_sync(0xffffffffu, part, off, 16);
            if (oq == 0) {
                float sc = part + bs2v;
                g_scores[b][i][j]  = sc;
                g_scoresT[b][j][i] = sc;
            }
        }
    }
}

// ---------------- DP backpointers (transposed reads + prefetch) ----------------
__global__ void dp_k()
{
    int b = blockIdx.x, t = threadIdx.x; // 64 threads
    __shared__ float best[SS];
    __shared__ float rv[2];
    __shared__ int ri[2];
    for (int p = t; p < SS; p += 64) best[p] = 0.0f;
    if (t == 0) g_backptr[b][0] = 0;
    __syncthreads();
    float sc_next = g_scoresT[b][1][t];   // i=1: start=0
    for (int i = 1; i < SS; i++) {
        int start = (i > WSEG) ? (i - WSEG) : 0;
        float sc = sc_next;
        if (i + 1 < SS) {
            int st2 = (i + 1 > WSEG) ? (i + 1 - WSEG) : 0;
            sc_next = g_scoresT[b][i + 1][st2 + t];
        }
        int j = start + t;
        float v = (j < i) ? best[j] + sc : -1000000000.0f;
        int idx = j;
#pragma unroll
        for (int off = 16; off > 0; off >>= 1) {
            float ov = __shfl_down_sync(0xffffffffu, v, off);
            int oi = __shfl_down_sync(0xffffffffu, idx, off);
            if (ov > v || (ov == v && oi < idx)) { v = ov; idx = oi; }
        }
        if ((t & 31) == 0) { rv[t >> 5] = v; ri[t >> 5] = idx; }
        __syncthreads();
        if (t == 0) {
            float v0 = rv[0], v1 = rv[1];
            int i0 = ri[0], i1 = ri[1];
            if (v1 > v0 || (v1 == v0 && i1 < i0)) { v0 = v1; i0 = i1; }
            best[i] = v0;
            g_backptr[b][i] = i0;
        }
        __syncthreads();
    }
}

// ---------------- backtrack + output bmask/pred_scores ----------------
__global__ void backtrack_k(const int* __restrict__ lengths, float* __restrict__ out)
{
    int t = threadIdx.x; // 256
    for (int p = t; p < BB * SS; p += 256) out[21504 + p] = 0.0f;
    __syncthreads();
    if (t < BB) {
        int b = t;
        int cur = lengths[b] - 1;
        float acc = 0.0f;
        for (int it = 0; it < SS; it++) {
            out[21504 + b * SS + cur] = 1.0f;
            int prev = g_backptr[b][cur];
            if (cur > 0) {
                acc += g_scores[b][prev][cur];
                cur = prev;
            } else {
                cur = 0;
            }
        }
        out[22016 + b] = acc;
    }
}

// ---------------- launch ----------------
extern "C" void kernel_launch(void* const* d_in, const int* in_sizes, int n_in,
                              void* d_out, int out_size)
{
    const float* x       = (const float*)d_in[0];
    const int*   lengths = (const int*)d_in[1];
    const float* wih0f = (const float*)d_in[2];
    const float* whh0f = (const float*)d_in[3];
    const float* bl0f  = (const float*)d_in[4];
    const float* wih0b = (const float*)d_in[5];
    const float* whh0b = (const float*)d_in[6];
    const float* bl0b  = (const float*)d_in[7];
    const float* wih1f = (const float*)d_in[8];
    const float* whh1f = (const float*)d_in[9];
    const float* bl1f  = (const float*)d_in[10];
    const float* wih1b = (const float*)d_in[11];
    const float* whh1b = (const float*)d_in[12];
    const float* bl1b  = (const float*)d_in[13];
    const float* a_s0 = (const float*)d_in[14];
    const float* w_s1 = (const float*)d_in[15];
    const float* b_s1 = (const float*)d_in[16];
    const float* a_s1 = (const float*)d_in[17];
    const float* w_s2 = (const float*)d_in[18];
    const float* b_s2 = (const float*)d_in[19];
    const float* a_c0 = (const float*)d_in[20];
    const float* w_c1 = (const float*)d_in[21];
    const float* b_c1 = (const float*)d_in[22];
    const float* a_c1 = (const float*)d_in[23];
    const float* w_c2 = (const float*)d_in[24];
    const float* b_c2 = (const float*)d_in[25];
    const float* a_b0 = (const float*)d_in[26];
    const float* w_b1 = (const float*)d_in[27];
    const float* b_b1 = (const float*)d_in[28];
    const float* a_b1 = (const float*)d_in[29];
    const float* w_b2 = (const float*)d_in[30];
    const float* b_b2 = (const float*)d_in[31];
    float* out = (float*)d_out;

    const int SCORES_SMEM = 256 * 4 + 64 * T2ROW * 8;   // ~67.6 KB
    cudaFuncSetAttribute(scores_k, cudaFuncAttributeMaxDynamicSharedMemorySize, SCORES_SMEM);

    prep_k<<<512, 256>>>(wih0f, wih0b, wih1f, wih1b, w_s1, w_c1, w_b1);

    inproj_k<INP><<<dim3(SS / 8, BB, 2), 512>>>(x, bl0f, bl0b, 0);
    recur_k<<<dim3(4, 4), 256>>>(whh0f, whh0b, 0);
    inproj_k<F2><<<dim3(SS / 8, BB, 2), 512>>>(x, bl1f, bl1b, 1);
    recur_k<<<dim3(4, 4), 256>>>(whh1f, whh1b, 1);

    cumsum_k<<<BB, F2>>>();
    determ_k<<<dim3(SS, BB), 128>>>(a_s0, b_s1);
    clsbin_k<<<dim3(SS, BB), 128>>>(a_c0, b_c1, a_c1, w_c2, b_c2,
                                    a_b0, b_b1, a_b1, w_b2, b_b2, out);
    scores_k<<<dim3(SS, BB), 256, SCORES_SMEM>>>(a_s0, a_s1, w_s2, b_s2);
    dp_k<<<BB, 64>>>();
    backtrack_k<<<1, 256>>>(lengths, out);
}

// round 7
// speedup vs baseline: 2.9871x; 1.1320x over previous
#include <cuda_runtime.h>
#include <math.h>
#include <stdint.h>

// Problem constants
#define BB   2
#define SS   256
#define INP  80
#define HID  128
#define F2   256
#define G4   512   // 4*HID
#define NCC  40
#define WSEG 64

typedef unsigned long long u64;

// ---------------- device scratch (no allocation allowed) ----------------
__device__ float g_WihT0[2][INP][G4];    // [dir][i][g]
__device__ float g_WihT1[2][F2][G4];
__device__ float g_pre[2][BB][SS][G4];   // [dir][b][s][g]  (reused per layer)
__device__ float g_rnn[2][BB][SS][F2];   // [layer][b][s][f]
__device__ float g_cum[BB][SS][F2];
__device__ float g_WcT[F2][128];         // w_s1 c-part transposed, o padded 100->128 (zeros)
__device__ float g_WdT[F2][128];
__device__ float g_WeT[F2][128];
__device__ float g_wc1T[F2][80];
__device__ float g_wb1T[F2][80];
__device__ float g_dterm[BB][SS][128];   // prelu(rnn_i)@Wd^T + b_s1 (padded)
__device__ float g_eterm[BB][SS][128];   // prelu(rnn_j)@We^T
__device__ float g_scoresT[BB][SS][SS];  // scoresT[b][j][i] = scores[i][j] (DP reads rows)

__device__ __forceinline__ float preluf(float x, float a) { return x >= 0.0f ? x : a * x; }
__device__ __forceinline__ float sig_fast(float x) { return __fdividef(1.0f, 1.0f + __expf(-x)); }
__device__ __forceinline__ float tanh_fast(float x) { return __fdividef(2.0f, 1.0f + __expf(-2.0f * x)) - 1.0f; }

// ---------------- f32x2 packed math helpers ----------------
__device__ __forceinline__ void fma2(u64& acc, u64 a, u64 b) {
    asm("fma.rn.f32x2 %0, %1, %2, %0;" : "+l"(acc) : "l"(a), "l"(b));
}
__device__ __forceinline__ u64 packf2(float lo, float hi) {
    u64 r; asm("mov.b64 %0, {%1, %2};" : "=l"(r) : "f"(lo), "f"(hi)); return r;
}
__device__ __forceinline__ float2 unpackf2(u64 v) {
    float2 r; asm("mov.b64 {%0, %1}, %2;" : "=f"(r.x), "=f"(r.y) : "l"(v)); return r;
}

// ---------------- cluster / mbarrier helpers ----------------
__device__ __forceinline__ uint32_t ctarank() {
    uint32_t r; asm("mov.u32 %0, %%cluster_ctarank;" : "=r"(r)); return r;
}
__device__ __forceinline__ uint32_t mapa_u32(uint32_t addr, uint32_t rank) {
    uint32_t r; asm("mapa.shared::cluster.u32 %0, %1, %2;" : "=r"(r) : "r"(addr), "r"(rank));
    return r;
}
__device__ __forceinline__ void st_async_f64(uint32_t raddr, u64 v, uint32_t rmbar) {
    asm volatile("st.async.shared::cluster.mbarrier::complete_tx::bytes.b64 [%0], %1, [%2];"
                 :: "r"(raddr), "l"(v), "r"(rmbar) : "memory");
}
__device__ __forceinline__ void mbar_init(uint32_t mbar, uint32_t count) {
    asm volatile("mbarrier.init.shared.b64 [%0], %1;" :: "r"(mbar), "r"(count) : "memory");
}
__device__ __forceinline__ void mbar_expect_tx(uint32_t mbar, uint32_t tx) {
    asm volatile("mbarrier.arrive.expect_tx.shared.b64 _, [%0], %1;" :: "r"(mbar), "r"(tx) : "memory");
}
__device__ __forceinline__ void mbar_wait(uint32_t mbar, uint32_t parity) {
    asm volatile(
        "{\n\t.reg .pred P;\n\t"
        "WL_%=:\n\t"
        "mbarrier.try_wait.parity.acquire.cluster.shared::cta.b64 P, [%0], %1, 0x989680;\n\t"
        "@P bra.uni WD_%=;\n\t"
        "bra.uni WL_%=;\n\t"
        "WD_%=:\n\t}"
        :: "r"(mbar), "r"(parity) : "memory");
}
__device__ __forceinline__ void cluster_sync() {
    asm volatile("barrier.cluster.arrive.aligned;" ::: "memory");
    asm volatile("barrier.cluster.wait.aligned;" ::: "memory");
}

// ---------------- prep: transpose weights into friendly layouts ----------------
__global__ void prep_k(const float* __restrict__ wih0f,
                       const float* __restrict__ wih0b,
                       const float* __restrict__ wih1f,
                       const float* __restrict__ wih1b,
                       const float* __restrict__ ws1,  const float* __restrict__ wc1,
                       const float* __restrict__ wb1)
{
    int idx = blockIdx.x * blockDim.x + threadIdx.x;
    int n = gridDim.x * blockDim.x;
    for (int p = idx; p < 2 * INP * G4; p += n) {
        int d = p / (INP * G4), r = p % (INP * G4), i = r / G4, g = r % G4;
        g_WihT0[d][i][g] = (d ? wih0b : wih0f)[g * INP + i];
    }
    for (int p = idx; p < 2 * F2 * G4; p += n) {
        int d = p / (F2 * G4), r = p % (F2 * G4), i = r / G4, g = r % G4;
        g_WihT1[d][i][g] = (d ? wih1b : wih1f)[g * F2 + i];
    }
    for (int p = idx; p < F2 * 128; p += n) {
        int k = p / 128, o = p % 128;
        g_WcT[k][o] = (o < 100) ? ws1[o * 768 + k]        : 0.0f;
        g_WdT[k][o] = (o < 100) ? ws1[o * 768 + 256 + k]  : 0.0f;
        g_WeT[k][o] = (o < 100) ? ws1[o * 768 + 512 + k]  : 0.0f;
    }
    for (int p = idx; p < F2 * 80; p += n) {
        int k = p / 80, o = p % 80;
        g_wc1T[k][o] = wc1[o * F2 + k];
        g_wb1T[k][o] = wb1[o * F2 + k];
    }
}

// ---------------- input projection: pre = x @ Wih^T + b ----------------
// s-tile 4, i-unroll 8 (MLP ~8 on W stream), 512 threads.
template <int INDIM>
__global__ void inproj_k(const float* __restrict__ x0,
                         const float* __restrict__ bias_f, const float* __restrict__ bias_b,
                         int layer)
{
    int st = blockIdx.x * 4, b = blockIdx.y, d = blockIdx.z, g = threadIdx.x;
    __shared__ float xs[4][INDIM];
    const float* xin = layer ? &g_rnn[0][0][0][0] : x0;
    for (int p = g; p < 4 * INDIM; p += 512) {
        int ss = p / INDIM, i = p % INDIM;
        xs[ss][i] = xin[(b * SS + st + ss) * INDIM + i];
    }
    __syncthreads();
    const float* W = (INDIM == INP) ? &g_WihT0[d][0][0] : &g_WihT1[d][0][0];
    float bg = (d ? bias_b : bias_f)[g];
    float acc[4] = {bg, bg, bg, bg};
    for (int i = 0; i < INDIM; i += 8) {
        float w[8];
#pragma unroll
        for (int q = 0; q < 8; q++) w[q] = W[(i + q) * G4 + g];
#pragma unroll
        for (int ss = 0; ss < 4; ss++) {
            float a = acc[ss];
#pragma unroll
            for (int q = 0; q < 8; q++) a = fmaf(xs[ss][i + q], w[q], a);
            acc[ss] = a;
        }
    }
#pragma unroll
    for (int ss = 0; ss < 4; ss++) g_pre[d][b][st + ss][g] = acc[ss];
}

// ---------------- LSTM recurrence: 4-CTA cluster, hidden-unit partition ----------------
// Rank r owns hidden units [32r, 32r+32): computes ALL 4 gates for them (local cell,
// no gate gather). Only h (32 floats/rank) is broadcast per step: 16 st.async.b64 x 3
// remotes = 384 bytes expected per rank. Two alternating mbarriers (2-step skew bound),
// double-buffered h.
__global__ void __launch_bounds__(256) __cluster_dims__(4, 1, 1)
recur_k(const float* __restrict__ whh_f, const float* __restrict__ whh_b, int layer)
{
    __shared__ alignas(16) float hbuf[2][HID];
    __shared__ float gloc[128];
    __shared__ alignas(8) u64 mbar[2];
    int t = threadIdx.x;
    uint32_t rank = ctarank();
    int chain = blockIdx.y;
    int b = chain >> 1, d = chain & 1;
    const float* __restrict__ whh = d ? whh_b : whh_f;
    int o = t >> 1, half = t & 1;           // 128 outputs x 2 k-halves
    int gate = o >> 5, up = o & 31;         // gate 0..3, unit-local 0..31
    int unit = (int)rank * 32 + up;         // global hidden unit
    int lane = t & 31;

    // weights: row gate*128+unit of w_hh, my 64-k half, as 32 packed f32x2 regs
    u64 wreg[32];
    {
        const ulonglong2* wrow = reinterpret_cast<const ulonglong2*>(
            whh + (gate * 128 + unit) * 128 + half * 64);
#pragma unroll
        for (int q = 0; q < 16; q++) { ulonglong2 u = wrow[q]; wreg[2 * q] = u.x; wreg[2 * q + 1] = u.y; }
    }

    if (t < HID) hbuf[0][t] = 0.0f;
    uint32_t mb0 = (uint32_t)__cvta_generic_to_shared(mbar);
    if (t == 0) { mbar_init(mb0, 1); mbar_init(mb0 + 8, 1); }
    __syncthreads();
    cluster_sync();   // peers' mbarriers + hbuf ready before any st.async

    uint32_t hb_loc = (uint32_t)__cvta_generic_to_shared(&hbuf[0][0]);
    uint32_t hb_r[3], mb_r[3];
    {
        int idx = 0;
#pragma unroll
        for (int r = 0; r < 4; r++) {
            if (r == (int)rank) continue;
            hb_r[idx] = mapa_u32(hb_loc, (uint32_t)r);
            mb_r[idx] = mapa_u32(mb0, (uint32_t)r);
            idx++;
        }
    }

    const float* __restrict__ preB = &g_pre[d][b][0][0];
    float* __restrict__ outB = &g_rnn[layer][b][0][0];
    float c = 0.0f;
    int preoff = gate * 128 + unit;

    int s0 = d ? (SS - 1) : 0;
    float pre = __ldg(&preB[s0 * G4 + preoff]);

    for (int step = 0; step < SS; ++step) {
        int p = step & 1;
        int s = d ? (SS - 1 - step) : step;
        if (t == 0) mbar_expect_tx(mb0 + 8u * (uint32_t)p, 384);

        // matvec over my 64-k half, weights in regs, h from hbuf[p]
        const ulonglong2* hp = reinterpret_cast<const ulonglong2*>(&hbuf[p][half * 64]);
        u64 a0 = 0, a1 = 0, a2 = 0, a3 = 0;
#pragma unroll
        for (int q = 0; q < 16; q++) {
            ulonglong2 h = hp[q];
            if (q & 1) { fma2(a2, wreg[2 * q], h.x); fma2(a3, wreg[2 * q + 1], h.y); }
            else       { fma2(a0, wreg[2 * q], h.x); fma2(a1, wreg[2 * q + 1], h.y); }
        }
        float2 f0 = unpackf2(a0), f1 = unpackf2(a1), f2 = unpackf2(a2), f3 = unpackf2(a3);
        float part = ((f0.x + f0.y) + (f1.x + f1.y)) + ((f2.x + f2.y) + (f3.x + f3.y));
        part += __shfl_xor_sync(0xffffffffu, part, 1);
        if (half == 0) gloc[o] = part + pre;

        // prefetch next pre (independent of h chain)
        if (step + 1 < SS) {
            int sn = d ? (SS - 2 - step) : (step + 1);
            pre = __ldg(&preB[sn * G4 + preoff]);
        }
        __syncthreads();   // gloc ready

        if (t < 32) {      // warp 0: local LSTM cell for my 32 units
            float gi = gloc[t], gf = gloc[32 + t], gg = gloc[64 + t], go = gloc[96 + t];
            c = sig_fast(gf) * c + sig_fast(gi) * tanh_fast(gg);
            float h = sig_fast(go) * tanh_fast(c);
            int pn = p ^ 1;
            hbuf[pn][(int)rank * 32 + t] = h;
            outB[s * F2 + d * HID + (int)rank * 32 + t] = h;
            float hA = __shfl_sync(0xffffffffu, h, 2 * lane);
            float hB = __shfl_sync(0xffffffffu, h, 2 * lane + 1);
            if (lane < 16) {
                u64 pk = packf2(hA, hB);
                uint32_t off = (uint32_t)(pn * (HID * 4) + ((int)rank * 32 + 2 * lane) * 4);
#pragma unroll
                for (int r = 0; r < 3; r++)
                    st_async_f64(hb_r[r] + off, pk, mb_r[r] + 8u * (uint32_t)p);
            }
        }
        mbar_wait(mb0 + 8u * (uint32_t)p, (step >> 1) & 1);
        __syncthreads();   // hbuf[p^1] (local STS + remote arrivals) visible to all warps
    }
    cluster_sync();
}

// ---------------- cumsum over time ----------------
__global__ void cumsum_k()
{
    int b = blockIdx.x, k = threadIdx.x; // 256
    float run = 0.0f;
#pragma unroll 4
    for (int s = 0; s < SS; s++) {
        run += g_rnn[1][b][s][k];
        g_cum[b][s][k] = run;
    }
}

// ---------------- dterm/eterm precompute ----------------
__global__ void determ_k(const float* __restrict__ a_s0p, const float* __restrict__ bs1)
{
    int s = blockIdx.x, b = blockIdx.y, t = threadIdx.x; // 128
    __shared__ float pr[F2];
    float a0 = *a_s0p;
    for (int p = t; p < F2; p += 128) pr[p] = preluf(g_rnn[1][b][s][p], a0);
    __syncthreads();
    float ad = 0.0f, ae = 0.0f;
    for (int k = 0; k < F2; k++) {
        float p = pr[k];
        ad = fmaf(p, g_WdT[k][t], ad);
        ae = fmaf(p, g_WeT[k][t], ae);
    }
    g_dterm[b][s][t] = ad + ((t < 100) ? bs1[t] : 0.0f);
    g_eterm[b][s][t] = ae;
}

// ---------------- cls / bin MLPs ----------------
__global__ void clsbin_k(const float* __restrict__ ac0, const float* __restrict__ bc1,
                         const float* __restrict__ ac1, const float* __restrict__ wc2,
                         const float* __restrict__ bc2,
                         const float* __restrict__ ab0, const float* __restrict__ bb1,
                         const float* __restrict__ ab1, const float* __restrict__ wb2,
                         const float* __restrict__ bb2, float* __restrict__ out)
{
    int s = blockIdx.x, b = blockIdx.y, t = threadIdx.x; // 128
    __shared__ float pr[F2];
    __shared__ float h1[80];
    float a = *ac0;
    for (int p = t; p < F2; p += 128) pr[p] = preluf(g_rnn[1][b][s][p], a);
    __syncthreads();
    if (t < 80) {
        float acc = bc1[t];
        for (int k = 0; k < F2; k++) acc = fmaf(pr[k], g_wc1T[k][t], acc);
        h1[t] = preluf(acc, *ac1);
    }
    __syncthreads();
    if (t < NCC) {
        float acc = bc2[t];
        for (int q = 0; q < 80; q++) acc = fmaf(h1[q], wc2[t * 80 + q], acc);
        out[(b * SS + s) * NCC + t] = acc;
    }
    __syncthreads();
    a = *ab0;
    for (int p = t; p < F2; p += 128) pr[p] = preluf(g_rnn[1][b][s][p], a);
    __syncthreads();
    if (t < 80) {
        float acc = bb1[t];
        for (int k = 0; k < F2; k++) acc = fmaf(pr[k], g_wb1T[k][t], acc);
        h1[t] = preluf(acc, *ab1);
    }
    __syncthreads();
    if (t < 2) {
        float acc = bb2[t];
        for (int q = 0; q < 80; q++) acc = fmaf(h1[q], wb2[t * 80 + q], acc);
        out[20480 + (b * SS + s) * 2 + t] = acc;
    }
}

// ---------------- pairwise scores: f32x2 packed, block=(i,b), 256 threads ----------------
#define T2ROW 130
__global__ void __launch_bounds__(256) scores_k(const float* __restrict__ a_s0p,
                         const float* __restrict__ a_s1p,
                         const float* __restrict__ ws2, const float* __restrict__ bs2)
{
    extern __shared__ float smd[];
    float* cum_i = smd;                                  // 256 floats
    u64* T2 = reinterpret_cast<u64*>(smd + 256);         // [64][T2ROW]
    int i = blockIdx.x, b = blockIdx.y, tid = threadIdx.x;
    int oq = tid & 15, jg = tid >> 4;   // 16 output-groups x 16 j-groups (4 j each)
    float a0 = *a_s0p, a1 = *a_s1p;
    for (int p = tid; p < F2; p += 256) cum_i[p] = g_cum[b][i][p];
    float dt[8], w2v[8];
#pragma unroll
    for (int r = 0; r < 8; r++) {
        int o = oq * 8 + r;
        dt[r] = g_dterm[b][i][o];
        w2v[r] = (o < 100) ? ws2[o] : 0.0f;
    }
    float bs2v = bs2[0];
    __syncthreads();
    const ulonglong2* __restrict__ W2 = reinterpret_cast<const ulonglong2*>(&g_WcT[0][0]);
    for (int tile = 0; tile < 4; tile++) {
        int j0 = tile * 64;
        u64 acc[4][4];
#pragma unroll
        for (int r4 = 0; r4 < 4; r4++)
#pragma unroll
            for (int p2 = 0; p2 < 4; p2++) acc[r4][p2] = 0ull;

        for (int kh = 0; kh < 2; kh++) {
            int kb = kh * 128;
            for (int p = tid; p < 64 * 128; p += 256) {
                int lj = p >> 7, k = p & 127;
                float v = preluf(g_cum[b][j0 + lj][kb + k] - cum_i[kb + k], a0);
                T2[lj * T2ROW + k] = packf2(v, v);
            }
            __syncthreads();
            const u64* Ta = &T2[(jg * 4 + 0) * T2ROW];
            const u64* Tb = &T2[(jg * 4 + 1) * T2ROW];
            const u64* Tc = &T2[(jg * 4 + 2) * T2ROW];
            const u64* Td = &T2[(jg * 4 + 3) * T2ROW];
#pragma unroll 2
            for (int k = 0; k < 128; k++) {
                ulonglong2 wA = W2[(kb + k) * 32 + 2 * oq];
                ulonglong2 wB = W2[(kb + k) * 32 + 2 * oq + 1];
                u64 t0 = Ta[k], t1 = Tb[k], t2 = Tc[k], t3 = Td[k];
                fma2(acc[0][0], t0, wA.x); fma2(acc[0][1], t0, wA.y);
                fma2(acc[0][2], t0, wB.x); fma2(acc[0][3], t0, wB.y);
                fma2(acc[1][0], t1, wA.x); fma2(acc[1][1], t1, wA.y);
                fma2(acc[1][2], t1, wB.x); fma2(acc[1][3], t1, wB.y);
                fma2(acc[2][0], t2, wA.x); fma2(acc[2][1], t2, wA.y);
                fma2(acc[2][2], t2, wB.x); fma2(acc[2][3], t2, wB.y);
                fma2(acc[3][0], t3, wA.x); fma2(acc[3][1], t3, wA.y);
                fma2(acc[3][2], t3, wB.x); fma2(acc[3][3], t3, wB.y);
            }
            __syncthreads();
        }
#pragma unroll
        for (int r4 = 0; r4 < 4; r4++) {
            int j = j0 + jg * 4 + r4;
            float part = 0.0f;
#pragma unroll
            for (int p2 = 0; p2 < 4; p2++) {
                float2 f = unpackf2(acc[r4][p2]);
                int r = 2 * p2, o = oq * 8 + r;
                float h0 = f.x + dt[r]     + g_eterm[b][j][o];
                float h1 = f.y + dt[r + 1] + g_eterm[b][j][o + 1];
                part = fmaf(preluf(h0, a1), w2v[r],     part);
                part = fmaf(preluf(h1, a1), w2v[r + 1], part);
            }
#pragma unroll
            for (int off = 8; off > 0; off >>= 1)
                part += __shfl_down_sync(0xffffffffu, part, off, 16);
            if (oq == 0) g_scoresT[b][j][i] = part + bs2v;
        }
    }
}

// ---------------- DP backpointers + fused backtrack ----------------
__global__ void dp_k(const int* __restrict__ lengths, float* __restrict__ out)
{
    int b = blockIdx.x, t = threadIdx.x; // 64 threads
    __shared__ float best[SS];
    __shared__ int bptr[SS];
    __shared__ float rv[2];
    __shared__ int ri[2];
    for (int p = t; p < SS; p += 64) { best[p] = 0.0f; out[21504 + b * SS + p] = 0.0f; }
    if (t == 0) bptr[0] = 0;
    __syncthreads();
    float sc_next = g_scoresT[b][1][t];   // i=1: start=0
    for (int i = 1; i < SS; i++) {
        int start = (i > WSEG) ? (i - WSEG) : 0;
        float sc = sc_next;
        if (i + 1 < SS) {
            int st2 = (i + 1 > WSEG) ? (i + 1 - WSEG) : 0;
            sc_next = g_scoresT[b][i + 1][st2 + t];
        }
        int j = start + t;
        float v = (j < i) ? best[j] + sc : -1000000000.0f;
        int idx = j;
#pragma unroll
        for (int off = 16; off > 0; off >>= 1) {
            float ov = __shfl_down_sync(0xffffffffu, v, off);
            int oi = __shfl_down_sync(0xffffffffu, idx, off);
            if (ov > v || (ov == v && oi < idx)) { v = ov; idx = oi; }
        }
        if ((t & 31) == 0) { rv[t >> 5] = v; ri[t >> 5] = idx; }
        __syncthreads();
        if (t == 0) {
            float v0 = rv[0], v1 = rv[1];
            int i0 = ri[0], i1 = ri[1];
            if (v1 > v0 || (v1 == v0 && i1 < i0)) { v0 = v1; i0 = i1; }
            best[i] = v0;
            bptr[i] = i0;
        }
        __syncthreads();
    }
    // fused backtrack: pred_scores = best[len-1]; bmask via smem pointer chase
    if (t == 0) {
        int cur = lengths[b] - 1;
        out[22016 + b] = (cur > 0) ? best[cur] : 0.0f;
        for (int it = 0; it < SS; it++) {
            out[21504 + b * SS + cur] = 1.0f;
            if (cur > 0) cur = bptr[cur];
        }
    }
}

// ---------------- launch ----------------
extern "C" void kernel_launch(void* const* d_in, const int* in_sizes, int n_in,
                              void* d_out, int out_size)
{
    const float* x       = (const float*)d_in[0];
    const int*   lengths = (const int*)d_in[1];
    const float* wih0f = (const float*)d_in[2];
    const float* whh0f = (const float*)d_in[3];
    const float* bl0f  = (const float*)d_in[4];
    const float* wih0b = (const float*)d_in[5];
    const float* whh0b = (const float*)d_in[6];
    const float* bl0b  = (const float*)d_in[7];
    const float* wih1f = (const float*)d_in[8];
    const float* whh1f = (const float*)d_in[9];
    const float* bl1f  = (const float*)d_in[10];
    const float* wih1b = (const float*)d_in[11];
    const float* whh1b = (const float*)d_in[12];
    const float* bl1b  = (const float*)d_in[13];
    const float* a_s0 = (const float*)d_in[14];
    const float* w_s1 = (const float*)d_in[15];
    const float* b_s1 = (const float*)d_in[16];
    const float* a_s1 = (const float*)d_in[17];
    const float* w_s2 = (const float*)d_in[18];
    const float* b_s2 = (const float*)d_in[19];
    const float* a_c0 = (const float*)d_in[20];
    const float* w_c1 = (const float*)d_in[21];
    const float* b_c1 = (const float*)d_in[22];
    const float* a_c1 = (const float*)d_in[23];
    const float* w_c2 = (const float*)d_in[24];
    const float* b_c2 = (const float*)d_in[25];
    const float* a_b0 = (const float*)d_in[26];
    const float* w_b1 = (const float*)d_in[27];
    const float* b_b1 = (const float*)d_in[28];
    const float* a_b1 = (const float*)d_in[29];
    const float* w_b2 = (const float*)d_in[30];
    const float* b_b2 = (const float*)d_in[31];
    float* out = (float*)d_out;

    const int SCORES_SMEM = 256 * 4 + 64 * T2ROW * 8;   // ~67.6 KB
    cudaFuncSetAttribute(scores_k, cudaFuncAttributeMaxDynamicSharedMemorySize, SCORES_SMEM);

    prep_k<<<512, 256>>>(wih0f, wih0b, wih1f, wih1b, w_s1, w_c1, w_b1);

    inproj_k<INP><<<dim3(SS / 4, BB, 2), 512>>>(x, bl0f, bl0b, 0);
    recur_k<<<dim3(4, 4), 256>>>(whh0f, whh0b, 0);
    inproj_k<F2><<<dim3(SS / 4, BB, 2), 512>>>(x, bl1f, bl1b, 1);
    recur_k<<<dim3(4, 4), 256>>>(whh1f, whh1b, 1);

    cumsum_k<<<BB, F2>>>();
    determ_k<<<dim3(SS, BB), 128>>>(a_s0, b_s1);
    clsbin_k<<<dim3(SS, BB), 128>>>(a_c0, b_c1, a_c1, w_c2, b_c2,
                                    a_b0, b_b1, a_b1, w_b2, b_b2, out);
    scores_k<<<dim3(SS, BB), 256, SCORES_SMEM>>>(a_s0, a_s1, w_s2, b_s2);
    dp_k<<<BB, 64>>>(lengths, out);
}